// round 4
// baseline (speedup 1.0000x reference)
#include <cuda_runtime.h>

// Problem constants
#define NN      64
#define C_TOT   64
#define WIN     4096
#define FF      64
#define KW      9
#define OW      4088          // WIN - KW + 1
#define T_TILE  128
#define CHUNK   8             // channels per shared-memory chunk
#define NCHUNK  (C_TOT / CHUNK)
#define XCOLS   (T_TILE + KW - 1)   // 136 columns staged per row
#define OPITCH  66            // s_out row pitch (floats): 64 + 2 pad

// ---------- packed fp32x2 helpers ----------
__device__ __forceinline__ unsigned long long ffma2(unsigned long long a,
                                                    unsigned long long b,
                                                    unsigned long long c) {
    unsigned long long d;
    asm("fma.rn.f32x2 %0, %1, %2, %3;" : "=l"(d) : "l"(a), "l"(b), "l"(c));
    return d;
}
__device__ __forceinline__ float2 upk2(unsigned long long v) {
    float2 f;
    asm("mov.b64 {%0, %1}, %2;" : "=f"(f.x), "=f"(f.y) : "l"(v));
    return f;
}

// Shared memory (union):
//   phase 1:  x_d  : CHUNK*XCOLS float2 (duplicated x)      =  8704 B
//             fp_s : CHUNK*KW*32 float2 (filter pairs)      = 18432 B
//   phase 2:  s_out: T_TILE * OPITCH floats (transpose buf) = 33792 B
#define SMEM_BYTES 33792

__global__ __launch_bounds__(256, 2)
void conv1d_fpair_kernel(const float* __restrict__ x,
                         const float* __restrict__ filt,
                         const float* __restrict__ bias,
                         float* __restrict__ out)
{
    __shared__ __align__(16) unsigned char smem_raw[SMEM_BYTES];
    float2* x_d  = reinterpret_cast<float2*>(smem_raw);                 // [CHUNK][XCOLS]
    float2* fp_s = reinterpret_cast<float2*>(smem_raw + CHUNK * XCOLS * 8); // [CHUNK][KW][32]
    float*  s_out = reinterpret_cast<float*>(smem_raw);                 // [T_TILE][OPITCH]

    const int tid  = threadIdx.x;
    const int lane = tid & 31;        // filter pair index p: filters 2p, 2p+1
    const int wid  = tid >> 5;        // warp id -> t sub-tile
    const int n    = blockIdx.y;
    const int t0   = blockIdx.x * T_TILE;
    const int tw   = wid * 16;        // local t offset of this warp's 16 outputs

    unsigned long long acc[16];
    #pragma unroll
    for (int j = 0; j < 16; j++) acc[j] = 0ULL;

    const bool full = (t0 + XCOLS) <= WIN;   // all but the last t-tile

    for (int chunk = 0; chunk < NCHUNK; ++chunk) {
        const int c0 = chunk * CHUNK;
        if (chunk) __syncthreads();

        // ---- stage x chunk, duplicated: x_d[row][col] = (v, v) ----
        if (full) {
            #pragma unroll
            for (int i = tid; i < CHUNK * 34; i += 256) {   // 34 float4 per row
                int row = i / 34, c4 = i - row * 34;
                const float4 q = *reinterpret_cast<const float4*>(
                    x + ((size_t)n * C_TOT + c0 + row) * WIN + t0 + c4 * 4);
                float2* dst = &x_d[row * XCOLS + c4 * 4];
                dst[0] = make_float2(q.x, q.x);
                dst[1] = make_float2(q.y, q.y);
                dst[2] = make_float2(q.z, q.z);
                dst[3] = make_float2(q.w, q.w);
            }
        } else {
            for (int i = tid; i < CHUNK * XCOLS; i += 256) {
                int row = i / XCOLS, col = i - row * XCOLS;
                int t = t0 + col;
                float v = (t < WIN)
                    ? x[((size_t)n * C_TOT + c0 + row) * WIN + t] : 0.0f;
                x_d[row * XCOLS + col] = make_float2(v, v);
            }
        }

        // ---- stage filter pairs: fp_s[cc][w][p] = (filt[2p][c][w], filt[2p+1][c][w]) ----
        #pragma unroll
        for (int i = tid; i < CHUNK * KW * 32; i += 256) {
            int cc  = i / (KW * 32);
            int rem = i - cc * (KW * 32);
            int w   = rem >> 5;
            int p   = rem & 31;
            int c   = c0 + cc;
            float lo = filt[(2 * p    ) * (C_TOT * KW) + c * KW + w];
            float hi = filt[(2 * p + 1) * (C_TOT * KW) + c * KW + w];
            fp_s[i] = make_float2(lo, hi);
        }
        __syncthreads();

        // ---- compute: CHUNK channels, 9-tap FIR, zero packing ----
        #pragma unroll 1
        for (int cc = 0; cc < CHUNK; ++cc) {
            // x window: 24 broadcast LDS.64 (all lanes same address)
            unsigned long long xv[24];
            const unsigned long long* xrow = reinterpret_cast<const unsigned long long*>(
                &x_d[cc * XCOLS + tw]);
            #pragma unroll
            for (int m = 0; m < 24; m++) xv[m] = xrow[m];

            const unsigned long long* fprow = reinterpret_cast<const unsigned long long*>(
                &fp_s[cc * (KW * 32) + lane]);
            #pragma unroll
            for (int w = 0; w < KW; ++w) {
                const unsigned long long fp = fprow[w * 32];  // conflict-free LDS.64
                #pragma unroll
                for (int j = 0; j < 16; ++j)
                    acc[j] = ffma2(xv[j + w], fp, acc[j]);
            }
        }
    }

    // ---- transpose through shared: s_out[t_local][f] ----
    __syncthreads();   // everyone done reading x_d/fp_s (aliased by s_out)
    #pragma unroll
    for (int j = 0; j < 16; ++j) {
        float2 v = upk2(acc[j]);     // (f=2p, f=2p+1) at t_local = tw + j
        *reinterpret_cast<float2*>(&s_out[(tw + j) * OPITCH + 2 * lane]) = v;
    }
    __syncthreads();

    // ---- coalesced store + bias: out[n][f][t0 + tl] = s_out[tl][f] + 64*bias[f] ----
    #pragma unroll
    for (int r = 0; r < 32; ++r) {
        int e  = r * 256 + tid;       // e in [0, 8192)
        int f  = e >> 7;              // 0..63
        int tl = e & 127;
        int t  = t0 + tl;
        if (t < OW) {
            float v = s_out[tl * OPITCH + f] + 64.0f * __ldg(&bias[f]);
            out[((size_t)n * FF + f) * OW + t] = v;
        }
    }
}

extern "C" void kernel_launch(void* const* d_in, const int* in_sizes, int n_in,
                              void* d_out, int out_size) {
    const float* x    = (const float*)d_in[0];   // [64,64,4096]
    const float* filt = (const float*)d_in[1];   // [64,64,9]
    const float* bias = (const float*)d_in[2];   // [64]
    float* out = (float*)d_out;                  // [64,64,4088]

    dim3 grid((OW + T_TILE - 1) / T_TILE, NN);   // (32, 64)
    conv1d_fpair_kernel<<<grid, 256>>>(x, filt, bias, out);
}

// round 8
// speedup vs baseline: 1.8967x; 1.8967x over previous
#include <cuda_runtime.h>
#include <cstdint>

// ---------------- problem constants ----------------
#define NN      64
#define C_TOT   64
#define WIN     4096
#define FF      64
#define KW      9
#define OW      4088
#define T_TILE  128
#define XCOLS   136          // T_TILE + KW - 1
#define NTHREADS 256

// smem layout (dynamic)
#define SMEM_XS     0                      // 64*136 floats = 34816 B
#define SMEM_B      34816                  // 4096 float2   = 32768 B
#define SMEM_BIAS   67584                  // 64 floats     =   256 B
#define SMEM_TOTAL  67840

// pre-split filter in B-fragment order: [w][co][j][r][lane] -> (hi, lo)
__device__ float2 g_fB[KW][8][8][2][32];

// hi = RN to tf32 (10-bit mantissa); lo = exact residual
__device__ __forceinline__ void split_tf32(float v, float& hi, float& lo) {
    uint32_t u = __float_as_uint(v);
    uint32_t h = (u + 0x00001000u) & 0xFFFFE000u;
    hi = __uint_as_float(h);
    lo = v - hi;
}

__device__ __forceinline__ void mma_tf32(float* d, const uint32_t* a,
                                         uint32_t b0, uint32_t b1) {
    asm volatile(
        "mma.sync.aligned.m16n8k8.row.col.f32.tf32.tf32.f32 "
        "{%0,%1,%2,%3}, {%4,%5,%6,%7}, {%8,%9}, {%0,%1,%2,%3};"
        : "+f"(d[0]), "+f"(d[1]), "+f"(d[2]), "+f"(d[3])
        : "r"(a[0]), "r"(a[1]), "r"(a[2]), "r"(a[3]), "r"(b0), "r"(b1));
}

// ---------------- prep: split filter into fragment-ordered hi/lo ----------------
__global__ void prep_filter_kernel(const float* __restrict__ filt) {
    int e = blockIdx.x * blockDim.x + threadIdx.x;
    if (e >= KW * 4096) return;
    int w    = e / 4096;
    int rem  = e - w * 4096;
    int co   = rem >> 9;
    int j    = (rem >> 6) & 7;
    int r    = (rem >> 5) & 1;
    int lane = rem & 31;
    int f = 8 * j + (lane >> 2);
    int c = 8 * co + (lane & 3) + 4 * r;
    float v = filt[f * (C_TOT * KW) + c * KW + w];
    float hi, lo; split_tf32(v, hi, lo);
    reinterpret_cast<float2*>(g_fB)[e] = make_float2(hi, lo);
}

// ---------------- main: implicit-GEMM conv via tf32 mma.sync ----------------
__global__ __launch_bounds__(NTHREADS, 2)
void conv1d_mma_kernel(const float* __restrict__ x,
                       const float* __restrict__ bias,
                       float* __restrict__ out)
{
    extern __shared__ __align__(16) unsigned char smem[];
    float*  xs     = reinterpret_cast<float*>(smem + SMEM_XS);   // [64][136]
    float2* Bs     = reinterpret_cast<float2*>(smem + SMEM_B);   // [co][j][r][lane]
    float*  bias_s = reinterpret_cast<float*>(smem + SMEM_BIAS);

    const int tid  = threadIdx.x;
    const int lane = tid & 31;
    const int wid  = tid >> 5;        // 8 warps -> m0 = wid*16
    const int m0   = wid * 16;
    const int n    = blockIdx.y;
    const int t0   = blockIdx.x * T_TILE;

    // ---- stage x window [64 c][136 t], zero-padded past WIN ----
    const float* xn = x + (size_t)n * C_TOT * WIN;
    if (t0 + XCOLS <= WIN) {
        #pragma unroll
        for (int i = tid; i < C_TOT * 34; i += NTHREADS) {
            int c = i / 34, q = i - c * 34;
            const float4 v = *reinterpret_cast<const float4*>(xn + (size_t)c * WIN + t0 + q * 4);
            *reinterpret_cast<float4*>(&xs[c * XCOLS + q * 4]) = v;
        }
    } else {
        for (int i = tid; i < C_TOT * XCOLS; i += NTHREADS) {
            int c = i / XCOLS, col = i - c * XCOLS;
            int t = t0 + col;
            xs[c * XCOLS + col] = (t < WIN) ? xn[(size_t)c * WIN + t] : 0.0f;
        }
    }
    if (tid < FF) bias_s[tid] = 64.0f * bias[tid];

    float acc[8][4];
    #pragma unroll
    for (int j = 0; j < 8; j++)
        #pragma unroll
        for (int r = 0; r < 4; r++) acc[j][r] = 0.0f;

    const int q4 = lane >> 2;          // 0..7 (m / n sub-index)
    const int k4 = lane & 3;           // 0..3 (k sub-index)

    for (int w = 0; w < KW; ++w) {
        __syncthreads();               // Bs free (prev w done; first w: after x staging)
        // ---- stage B(w): pure coalesced copy, 4096 float2 ----
        {
            const float4* src = reinterpret_cast<const float4*>(&g_fB[w][0][0][0][0]);
            float4* dst = reinterpret_cast<float4*>(Bs);
            #pragma unroll
            for (int i = tid; i < 2048; i += NTHREADS) dst[i] = src[i];
        }
        __syncthreads();

        #pragma unroll
        for (int co = 0; co < 8; ++co) {
            // ---- A fragment: 4 conflict-free LDS + tf32 split ----
            const float* ab = &xs[(co * 8 + k4) * XCOLS + w + m0 + q4];
            float v0 = ab[0], v1 = ab[8], v2 = ab[4 * XCOLS], v3 = ab[4 * XCOLS + 8];
            float h, l;
            uint32_t ah[4], al[4];
            split_tf32(v0, h, l); ah[0] = __float_as_uint(h); al[0] = __float_as_uint(l);
            split_tf32(v1, h, l); ah[1] = __float_as_uint(h); al[1] = __float_as_uint(l);
            split_tf32(v2, h, l); ah[2] = __float_as_uint(h); al[2] = __float_as_uint(l);
            split_tf32(v3, h, l); ah[3] = __float_as_uint(h); al[3] = __float_as_uint(l);

            #pragma unroll
            for (int jg = 0; jg < 2; ++jg) {
                // ---- B fragments for 4 j-tiles: 8 conflict-free LDS.64 ----
                float2 b0p[4], b1p[4];
                #pragma unroll
                for (int jj = 0; jj < 4; ++jj) {
                    int j = jg * 4 + jj;
                    b0p[jj] = Bs[(co * 16 + j * 2 + 0) * 32 + lane];
                    b1p[jj] = Bs[(co * 16 + j * 2 + 1) * 32 + lane];
                }
                // term 0: A_hi * B_hi
                #pragma unroll
                for (int jj = 0; jj < 4; ++jj)
                    mma_tf32(acc[jg * 4 + jj], ah,
                             __float_as_uint(b0p[jj].x), __float_as_uint(b1p[jj].x));
                // term 1: A_hi * B_lo
                #pragma unroll
                for (int jj = 0; jj < 4; ++jj)
                    mma_tf32(acc[jg * 4 + jj], ah,
                             __float_as_uint(b0p[jj].y), __float_as_uint(b1p[jj].y));
                // term 2: A_lo * B_hi
                #pragma unroll
                for (int jj = 0; jj < 4; ++jj)
                    mma_tf32(acc[jg * 4 + jj], al,
                             __float_as_uint(b0p[jj].x), __float_as_uint(b1p[jj].x));
            }
        }
    }

    // ---- epilogue: + 64*bias[f]; direct stores (32B-contiguous per f group) ----
    float* on = out + (size_t)n * FF * OW;
    const int ta = t0 + m0 + q4;
    const int tb = ta + 8;
    #pragma unroll
    for (int j = 0; j < 8; ++j) {
        const int f0 = 8 * j + 2 * k4;
        const float bb0 = bias_s[f0], bb1 = bias_s[f0 + 1];
        if (ta < OW) {
            on[(size_t)f0 * OW + ta]       = acc[j][0] + bb0;
            on[(size_t)(f0 + 1) * OW + ta] = acc[j][1] + bb1;
        }
        if (tb < OW) {
            on[(size_t)f0 * OW + tb]       = acc[j][2] + bb0;
            on[(size_t)(f0 + 1) * OW + tb] = acc[j][3] + bb1;
        }
    }
}

// =====================================================================
extern "C" void kernel_launch(void* const* d_in, const int* in_sizes, int n_in,
                              void* d_out, int out_size) {
    const float* x    = (const float*)d_in[0];   // [64,64,4096]
    const float* filt = (const float*)d_in[1];   // [64,64,9]
    const float* bias = (const float*)d_in[2];   // [64]
    float* out = (float*)d_out;                  // [64,64,4088]

    cudaFuncSetAttribute(conv1d_mma_kernel,
                         cudaFuncAttributeMaxDynamicSharedMemorySize, SMEM_TOTAL);

    prep_filter_kernel<<<(KW * 4096 + 255) / 256, 256>>>(filt);

    dim3 grid(OW / T_TILE + 1, NN);   // (32, 64)
    conv1d_mma_kernel<<<grid, NTHREADS, SMEM_TOTAL>>>(x, bias, out);
}

// round 9
// speedup vs baseline: 3.4411x; 1.8142x over previous
#include <cuda_runtime.h>
#include <cuda_bf16.h>
#include <cstdint>

// ---------------- problem constants ----------------
#define NN      64
#define C_TOT   64
#define WIN     4096
#define FF      64
#define KW      9
#define OW      4088
#define T_TILE  128
#define XCOLS   136          // T_TILE + KW - 1 (valid cols)
#define PITCH   140          // xs row pitch: (12c+t) banks conflict-free for A frags
#define NTHREADS 256

// smem layout (dynamic)
#define SMEM_XS     0                          // 64*140*4 = 35840 B
#define SMEM_B0     35840                      // 16384 B (1024 uint4)
#define SMEM_B1     52224                      // 16384 B
#define SMEM_BIAS   68608                      // 256 B
#define SMEM_TOTAL  68864

// pre-split bf16 filter in B-fragment order:
// g_fB[w][co(4)][j(8)][lane(32)] = {bhi0, bhi1, blo0, blo1}
__device__ uint4 g_fB[KW][4][8][32];

__device__ __forceinline__ uint32_t pack_bf16x2(float lo_elem, float hi_elem) {
    uint32_t r;   // low 16 bits <- lo_elem (first/lower k index)
    asm("cvt.rn.bf16x2.f32 %0, %1, %2;" : "=r"(r) : "f"(hi_elem), "f"(lo_elem));
    return r;
}
__device__ __forceinline__ float bf_lo_f(uint32_t p) { return __uint_as_float(p << 16); }
__device__ __forceinline__ float bf_hi_f(uint32_t p) { return __uint_as_float(p & 0xFFFF0000u); }

// hi = bf16 RN; lo = bf16 RN of exact residual (packed pair helpers)
__device__ __forceinline__ void split_pack(float v0, float v1,
                                           uint32_t& hi, uint32_t& lo) {
    hi = pack_bf16x2(v0, v1);
    lo = pack_bf16x2(v0 - bf_lo_f(hi), v1 - bf_hi_f(hi));
}

__device__ __forceinline__ void mma_bf16(float* d,
                                         uint32_t a0, uint32_t a1, uint32_t a2, uint32_t a3,
                                         uint32_t b0, uint32_t b1) {
    asm volatile(
        "mma.sync.aligned.m16n8k16.row.col.f32.bf16.bf16.f32 "
        "{%0,%1,%2,%3}, {%4,%5,%6,%7}, {%8,%9}, {%0,%1,%2,%3};"
        : "+f"(d[0]), "+f"(d[1]), "+f"(d[2]), "+f"(d[3])
        : "r"(a0), "r"(a1), "r"(a2), "r"(a3), "r"(b0), "r"(b1));
}

// ---------------- prep: split filter into fragment-ordered bf16 hi/lo ----------------
__global__ void prep_filter_bf16(const float* __restrict__ filt) {
    int e = blockIdx.x * blockDim.x + threadIdx.x;
    if (e >= KW * 4 * 8 * 32) return;
    int w    = e / 1024;
    int rem  = e - w * 1024;
    int co   = rem >> 8;
    int j    = (rem >> 5) & 7;
    int lane = rem & 31;
    int g = lane >> 2, k4 = lane & 3;
    int f  = 8 * j + g;
    int c0 = co * 16 + 2 * k4;

    const float* fr = filt + (size_t)f * (C_TOT * KW) + w;
    float v0 = fr[(c0    ) * KW];
    float v1 = fr[(c0 + 1) * KW];
    float v2 = fr[(c0 + 8) * KW];
    float v3 = fr[(c0 + 9) * KW];

    uint4 q;
    split_pack(v0, v1, q.x, q.z);   // b0: hi in .x, lo in .z
    split_pack(v2, v3, q.y, q.w);   // b1: hi in .y, lo in .w
    g_fB[w][co][j][lane] = q;
}

// ---------------- main: implicit-GEMM conv via bf16 m16n8k16 ----------------
__global__ __launch_bounds__(NTHREADS, 3)
void conv1d_bf16_mma_kernel(const float* __restrict__ x,
                            const float* __restrict__ bias,
                            float* __restrict__ out)
{
    extern __shared__ __align__(16) unsigned char smem[];
    float* xs     = reinterpret_cast<float*>(smem + SMEM_XS);   // [64][PITCH]
    uint4* Bs[2]  = { reinterpret_cast<uint4*>(smem + SMEM_B0),
                      reinterpret_cast<uint4*>(smem + SMEM_B1) };
    float* bias_s = reinterpret_cast<float*>(smem + SMEM_BIAS);

    const int tid  = threadIdx.x;
    const int lane = tid & 31;
    const int wid  = tid >> 5;        // 8 warps -> m0 = wid*16
    const int m0   = wid * 16;
    const int n    = blockIdx.y;
    const int t0   = blockIdx.x * T_TILE;

    // ---- stage x window [64 c][136 t] (pitch 140), zero-padded past WIN ----
    const float* xn = x + (size_t)n * C_TOT * WIN;
    if (t0 + XCOLS <= WIN) {
        #pragma unroll
        for (int i = tid; i < C_TOT * 34; i += NTHREADS) {
            int c = i / 34, q = i - c * 34;
            const float4 v = *reinterpret_cast<const float4*>(xn + (size_t)c * WIN + t0 + q * 4);
            *reinterpret_cast<float4*>(&xs[c * PITCH + q * 4]) = v;
        }
    } else {
        for (int i = tid; i < C_TOT * XCOLS; i += NTHREADS) {
            int c = i / XCOLS, col = i - c * XCOLS;
            int t = t0 + col;
            xs[c * PITCH + col] = (t < WIN) ? xn[(size_t)c * WIN + t] : 0.0f;
        }
    }
    if (tid < FF) bias_s[tid] = 64.0f * bias[tid];

    // ---- stage B(0) into buffer 0 ----
    {
        const uint4* src = &g_fB[0][0][0][0];
        #pragma unroll
        for (int i = tid; i < 1024; i += NTHREADS) Bs[0][i] = src[i];
    }

    float acc[8][4];
    #pragma unroll
    for (int j = 0; j < 8; j++)
        #pragma unroll
        for (int r = 0; r < 4; r++) acc[j][r] = 0.0f;

    const int g  = lane >> 2;          // m / n sub-index
    const int k4 = lane & 3;           // k sub-index

    for (int w = 0; w < KW; ++w) {
        __syncthreads();   // B(w) visible; buffer (w+1)&1 free (w-1's compute done)

        // ---- prefetch B(w+1) into the other buffer (overlaps compute) ----
        if (w + 1 < KW) {
            const uint4* src = &g_fB[w + 1][0][0][0];
            uint4* dst = Bs[(w + 1) & 1];
            #pragma unroll
            for (int i = tid; i < 1024; i += NTHREADS) dst[i] = src[i];
        }

        const uint4* Bw = Bs[w & 1];
        const float* xw = xs + w + m0;      // column base for this warp & tap

        #pragma unroll
        for (int co = 0; co < 4; ++co) {
            // ---- A fragment: 8 conflict-free scalar LDS + bf16 split ----
            const int cb = co * 16 + 2 * k4;
            const float* p0 = xw + (cb    ) * PITCH;
            const float* p1 = xw + (cb + 1) * PITCH;
            const float* p8 = xw + (cb + 8) * PITCH;
            const float* p9 = xw + (cb + 9) * PITCH;
            uint32_t ah0, ah1, ah2, ah3, al0, al1, al2, al3;
            split_pack(p0[g],     p1[g],     ah0, al0);   // (row g,   k 0..1)
            split_pack(p0[g + 8], p1[g + 8], ah1, al1);   // (row g+8, k 0..1)
            split_pack(p8[g],     p9[g],     ah2, al2);   // (row g,   k 8..9)
            split_pack(p8[g + 8], p9[g + 8], ah3, al3);   // (row g+8, k 8..9)

            #pragma unroll
            for (int jg = 0; jg < 2; ++jg) {
                // B fragments for 4 j-tiles: 4 conflict-free LDS.128
                uint4 bq[4];
                #pragma unroll
                for (int jj = 0; jj < 4; ++jj)
                    bq[jj] = Bw[co * 256 + (jg * 4 + jj) * 32 + lane];
                // term hh
                #pragma unroll
                for (int jj = 0; jj < 4; ++jj)
                    mma_bf16(acc[jg * 4 + jj], ah0, ah1, ah2, ah3, bq[jj].x, bq[jj].y);
                // term hl (A_hi * B_lo)
                #pragma unroll
                for (int jj = 0; jj < 4; ++jj)
                    mma_bf16(acc[jg * 4 + jj], ah0, ah1, ah2, ah3, bq[jj].z, bq[jj].w);
                // term lh (A_lo * B_hi)
                #pragma unroll
                for (int jj = 0; jj < 4; ++jj)
                    mma_bf16(acc[jg * 4 + jj], al0, al1, al2, al3, bq[jj].x, bq[jj].y);
            }
        }
    }

    // ---- epilogue: + 64*bias[f]; 2 contiguous floats per (j, row) ----
    float* on = out + (size_t)n * FF * OW;
    const int ta = t0 + m0 + g;
    const int tb = ta + 8;
    #pragma unroll
    for (int j = 0; j < 8; ++j) {
        const int f0 = 8 * j + 2 * k4;
        const float bb0 = bias_s[f0], bb1 = bias_s[f0 + 1];
        if (ta < OW) {
            on[(size_t)f0 * OW + ta]       = acc[j][0] + bb0;
            on[(size_t)(f0 + 1) * OW + ta] = acc[j][1] + bb1;
        }
        if (tb < OW) {
            on[(size_t)f0 * OW + tb]       = acc[j][2] + bb0;
            on[(size_t)(f0 + 1) * OW + tb] = acc[j][3] + bb1;
        }
    }
}

// =====================================================================
extern "C" void kernel_launch(void* const* d_in, const int* in_sizes, int n_in,
                              void* d_out, int out_size) {
    const float* x    = (const float*)d_in[0];   // [64,64,4096]
    const float* filt = (const float*)d_in[1];   // [64,64,9]
    const float* bias = (const float*)d_in[2];   // [64]
    float* out = (float*)d_out;                  // [64,64,4088]

    cudaFuncSetAttribute(conv1d_bf16_mma_kernel,
                         cudaFuncAttributeMaxDynamicSharedMemorySize, SMEM_TOTAL);

    prep_filter_bf16<<<(KW * 1024 + 255) / 256, 256>>>(filt);

    dim3 grid(OW / T_TILE + 1, NN);   // (32, 64)
    conv1d_bf16_mma_kernel<<<grid, NTHREADS, SMEM_TOTAL>>>(x, bias, out);
}

// round 10
// speedup vs baseline: 3.7413x; 1.0872x over previous
#include <cuda_runtime.h>
#include <cuda_bf16.h>
#include <cstdint>

// ---------------- problem constants ----------------
#define NN      64
#define C_TOT   64
#define WIN     4096
#define FF      64
#define KW      9
#define OW      4088
#define T_TILE  128
#define XCOLS   136          // T_TILE + KW - 1 (valid cols)
#define PITCH2  140          // xhi2/xlo2 row pitch (uint32): banks 12*k4+g distinct
#define NTHREADS 256

// smem layout (dynamic)
#define SMEM_XHI    0                          // 32*140*4 = 17920 B
#define SMEM_XLO    17920                      // 17920 B
#define SMEM_BIAS   35840                      // 256 B
#define SMEM_TOTAL  36096

// pre-split bf16 filter in B-fragment order:
// g_fB[w][co(4)][j(8)][lane(32)] = {bhi0, bhi1, blo0, blo1}
__device__ uint4 g_fB[KW][4][8][32];

__device__ __forceinline__ uint32_t pack_bf16x2(float lo_elem, float hi_elem) {
    uint32_t r;   // low 16 bits <- lo_elem (first/lower k index)
    asm("cvt.rn.bf16x2.f32 %0, %1, %2;" : "=r"(r) : "f"(hi_elem), "f"(lo_elem));
    return r;
}
__device__ __forceinline__ float bf_lo_f(uint32_t p) { return __uint_as_float(p << 16); }
__device__ __forceinline__ float bf_hi_f(uint32_t p) { return __uint_as_float(p & 0xFFFF0000u); }

// hi = bf16 RN pair; lo = bf16 RN pair of exact residuals
__device__ __forceinline__ void split_pack(float v0, float v1,
                                           uint32_t& hi, uint32_t& lo) {
    hi = pack_bf16x2(v0, v1);
    lo = pack_bf16x2(v0 - bf_lo_f(hi), v1 - bf_hi_f(hi));
}

__device__ __forceinline__ void mma_bf16(float* d,
                                         uint32_t a0, uint32_t a1, uint32_t a2, uint32_t a3,
                                         uint32_t b0, uint32_t b1) {
    asm volatile(
        "mma.sync.aligned.m16n8k16.row.col.f32.bf16.bf16.f32 "
        "{%0,%1,%2,%3}, {%4,%5,%6,%7}, {%8,%9}, {%0,%1,%2,%3};"
        : "+f"(d[0]), "+f"(d[1]), "+f"(d[2]), "+f"(d[3])
        : "r"(a0), "r"(a1), "r"(a2), "r"(a3), "r"(b0), "r"(b1));
}

// ---------------- prep: split filter into fragment-ordered bf16 hi/lo ----------------
__global__ void prep_filter_bf16(const float* __restrict__ filt) {
    int e = blockIdx.x * blockDim.x + threadIdx.x;
    if (e >= KW * 4 * 8 * 32) return;
    int w    = e / 1024;
    int rem  = e - w * 1024;
    int co   = rem >> 8;
    int j    = (rem >> 5) & 7;
    int lane = rem & 31;
    int g = lane >> 2, k4 = lane & 3;
    int f  = 8 * j + g;
    int c0 = co * 16 + 2 * k4;

    const float* fr = filt + (size_t)f * (C_TOT * KW) + w;
    float v0 = fr[(c0    ) * KW];
    float v1 = fr[(c0 + 1) * KW];
    float v2 = fr[(c0 + 8) * KW];
    float v3 = fr[(c0 + 9) * KW];

    uint4 q;
    split_pack(v0, v1, q.x, q.z);   // b0: hi in .x, lo in .z
    split_pack(v2, v3, q.y, q.w);   // b1: hi in .y, lo in .w
    g_fB[w][co][j][lane] = q;
}

// ---------------- main: implicit-GEMM conv via bf16 m16n8k16 ----------------
__global__ __launch_bounds__(NTHREADS, 3)
void conv1d_bf16_mma_kernel(const float* __restrict__ x,
                            const float* __restrict__ bias,
                            float* __restrict__ out)
{
    extern __shared__ __align__(16) unsigned char smem[];
    uint32_t* xhi2  = reinterpret_cast<uint32_t*>(smem + SMEM_XHI);  // [32][PITCH2]
    uint32_t* xlo2  = reinterpret_cast<uint32_t*>(smem + SMEM_XLO);  // [32][PITCH2]
    float*    bias_s = reinterpret_cast<float*>(smem + SMEM_BIAS);

    const int tid  = threadIdx.x;
    const int lane = tid & 31;
    const int wid  = tid >> 5;        // 8 warps -> m0 = wid*16
    const int m0   = wid * 16;
    const int n    = blockIdx.y;
    const int t0   = blockIdx.x * T_TILE;

    // ---- stage x window, pre-split to bf16 hi/lo and packed in c-pairs ----
    // xhi2[cp][t] = bf16x2( x[2cp][t0+t], x[2cp+1][t0+t] ) ; xlo2 = residuals
    const float* xn = x + (size_t)n * C_TOT * WIN;
    if (t0 + XCOLS <= WIN) {
        #pragma unroll
        for (int i = tid; i < 32 * 34; i += NTHREADS) {
            int cp = i / 34, q = i - cp * 34;
            const float* r0 = xn + (size_t)(2 * cp) * WIN + t0 + 4 * q;
            const float4 v0 = *reinterpret_cast<const float4*>(r0);
            const float4 v1 = *reinterpret_cast<const float4*>(r0 + WIN);
            uint4 h, l;
            split_pack(v0.x, v1.x, h.x, l.x);
            split_pack(v0.y, v1.y, h.y, l.y);
            split_pack(v0.z, v1.z, h.z, l.z);
            split_pack(v0.w, v1.w, h.w, l.w);
            *reinterpret_cast<uint4*>(&xhi2[cp * PITCH2 + 4 * q]) = h;
            *reinterpret_cast<uint4*>(&xlo2[cp * PITCH2 + 4 * q]) = l;
        }
    } else {
        for (int i = tid; i < 32 * XCOLS; i += NTHREADS) {
            int cp = i / XCOLS, col = i - cp * XCOLS;
            int t = t0 + col;
            float a = 0.0f, b = 0.0f;
            if (t < WIN) {
                a = xn[(size_t)(2 * cp) * WIN + t];
                b = xn[(size_t)(2 * cp + 1) * WIN + t];
            }
            uint32_t h, l;
            split_pack(a, b, h, l);
            xhi2[cp * PITCH2 + col] = h;
            xlo2[cp * PITCH2 + col] = l;
        }
    }
    if (tid < FF) bias_s[tid] = 64.0f * bias[tid];
    __syncthreads();        // the ONLY barrier

    float acc[8][4];
    #pragma unroll
    for (int j = 0; j < 8; j++)
        #pragma unroll
        for (int r = 0; r < 4; r++) acc[j][r] = 0.0f;

    const int g  = lane >> 2;          // m / n sub-index
    const int k4 = lane & 3;           // k sub-index

    for (int w = 0; w < KW; ++w) {
        const int col = w + m0 + g;    // t column for rows g / g+8 via +8

        #pragma unroll
        for (int co = 0; co < 4; ++co) {
            // ---- A fragment: 8 conflict-free LDS.32, zero conversion ----
            const uint32_t* hA = &xhi2[(co * 8 + k4) * PITCH2 + col];
            const uint32_t* hB = hA + 4 * PITCH2;       // k-pair 4+k4
            const uint32_t* lA = &xlo2[(co * 8 + k4) * PITCH2 + col];
            const uint32_t* lB = lA + 4 * PITCH2;
            uint32_t ah0 = hA[0], ah1 = hA[8], ah2 = hB[0], ah3 = hB[8];
            uint32_t al0 = lA[0], al1 = lA[8], al2 = lB[0], al3 = lB[8];

            #pragma unroll
            for (int jg = 0; jg < 2; ++jg) {
                // B fragments: 4 LDG.128, identical addresses across all warps/CTAs
                uint4 bq[4];
                #pragma unroll
                for (int jj = 0; jj < 4; ++jj)
                    bq[jj] = __ldg(&g_fB[w][co][jg * 4 + jj][lane]);
                // term hh
                #pragma unroll
                for (int jj = 0; jj < 4; ++jj)
                    mma_bf16(acc[jg * 4 + jj], ah0, ah1, ah2, ah3, bq[jj].x, bq[jj].y);
                // term hl (A_hi * B_lo)
                #pragma unroll
                for (int jj = 0; jj < 4; ++jj)
                    mma_bf16(acc[jg * 4 + jj], ah0, ah1, ah2, ah3, bq[jj].z, bq[jj].w);
                // term lh (A_lo * B_hi)
                #pragma unroll
                for (int jj = 0; jj < 4; ++jj)
                    mma_bf16(acc[jg * 4 + jj], al0, al1, al2, al3, bq[jj].x, bq[jj].y);
            }
        }
    }

    // ---- epilogue: + 64*bias[f]; 2 contiguous floats per (j, row) ----
    float* on = out + (size_t)n * FF * OW;
    const int ta = t0 + m0 + g;
    const int tb = ta + 8;
    #pragma unroll
    for (int j = 0; j < 8; ++j) {
        const int f0 = 8 * j + 2 * k4;
        const float bb0 = bias_s[f0], bb1 = bias_s[f0 + 1];
        if (ta < OW) {
            on[(size_t)f0 * OW + ta]       = acc[j][0] + bb0;
            on[(size_t)(f0 + 1) * OW + ta] = acc[j][1] + bb1;
        }
        if (tb < OW) {
            on[(size_t)f0 * OW + tb]       = acc[j][2] + bb0;
            on[(size_t)(f0 + 1) * OW + tb] = acc[j][3] + bb1;
        }
    }
}

// =====================================================================
extern "C" void kernel_launch(void* const* d_in, const int* in_sizes, int n_in,
                              void* d_out, int out_size) {
    const float* x    = (const float*)d_in[0];   // [64,64,4096]
    const float* filt = (const float*)d_in[1];   // [64,64,9]
    const float* bias = (const float*)d_in[2];   // [64]
    float* out = (float*)d_out;                  // [64,64,4088]

    cudaFuncSetAttribute(conv1d_bf16_mma_kernel,
                         cudaFuncAttributeMaxDynamicSharedMemorySize, SMEM_TOTAL);

    prep_filter_bf16<<<(KW * 1024 + 255) / 256, 256>>>(filt);

    dim3 grid(OW / T_TILE + 1, NN);   // (32, 64)
    conv1d_bf16_mma_kernel<<<grid, NTHREADS, SMEM_TOTAL>>>(x, bias, out);
}

// round 11
// speedup vs baseline: 4.4845x; 1.1987x over previous
#include <cuda_runtime.h>
#include <cuda_bf16.h>
#include <cstdint>

// ---------------- problem constants ----------------
#define NN      64
#define C_TOT   64
#define WIN     4096
#define FF      64
#define KW      9
#define OW      4088
#define T_TILE  256
#define XCOLS   263          // T_TILE + 8 - 1  (max col actually read)
#define XSTG    264          // staged cols in full path (mult of 4)
#define PITCH2  264          // 264 mod 32 == 8 -> banks 8*k4+g all distinct
#define NTHREADS 256

// smem layout (dynamic)
#define SMEM_XHI    0                          // 32*264*4 = 33792 B
#define SMEM_XLO    33792                      // 33792 B
#define SMEM_BIAS   67584                      // 256 B
#define SMEM_TOTAL  67840

// pre-split bf16 filter in B-fragment order:
// g_fB[w][co(4)][j(8)][lane(32)] = {bhi0, bhi1, blo0, blo1}
__device__ uint4 g_fB[KW][4][8][32];

__device__ __forceinline__ uint32_t pack_bf16x2(float lo_elem, float hi_elem) {
    uint32_t r;   // low 16 bits <- lo_elem (first/lower k index)
    asm("cvt.rn.bf16x2.f32 %0, %1, %2;" : "=r"(r) : "f"(hi_elem), "f"(lo_elem));
    return r;
}
__device__ __forceinline__ float bf_lo_f(uint32_t p) { return __uint_as_float(p << 16); }
__device__ __forceinline__ float bf_hi_f(uint32_t p) { return __uint_as_float(p & 0xFFFF0000u); }

// hi = bf16 RN pair; lo = bf16 RN pair of exact residuals
__device__ __forceinline__ void split_pack(float v0, float v1,
                                           uint32_t& hi, uint32_t& lo) {
    hi = pack_bf16x2(v0, v1);
    lo = pack_bf16x2(v0 - bf_lo_f(hi), v1 - bf_hi_f(hi));
}

__device__ __forceinline__ void mma_bf16(float* d, const uint32_t* a,
                                         uint32_t b0, uint32_t b1) {
    asm volatile(
        "mma.sync.aligned.m16n8k16.row.col.f32.bf16.bf16.f32 "
        "{%0,%1,%2,%3}, {%4,%5,%6,%7}, {%8,%9}, {%0,%1,%2,%3};"
        : "+f"(d[0]), "+f"(d[1]), "+f"(d[2]), "+f"(d[3])
        : "r"(a[0]), "r"(a[1]), "r"(a[2]), "r"(a[3]), "r"(b0), "r"(b1));
}

// ---------------- prep: split filter into fragment-ordered bf16 hi/lo ----------------
__global__ void prep_filter_bf16(const float* __restrict__ filt) {
    int e = blockIdx.x * blockDim.x + threadIdx.x;
    if (e >= KW * 4 * 8 * 32) return;
    int w    = e / 1024;
    int rem  = e - w * 1024;
    int co   = rem >> 8;
    int j    = (rem >> 5) & 7;
    int lane = rem & 31;
    int g = lane >> 2, k4 = lane & 3;
    int f  = 8 * j + g;
    int c0 = co * 16 + 2 * k4;

    const float* fr = filt + (size_t)f * (C_TOT * KW) + w;
    float v0 = fr[(c0    ) * KW];
    float v1 = fr[(c0 + 1) * KW];
    float v2 = fr[(c0 + 8) * KW];
    float v3 = fr[(c0 + 9) * KW];

    uint4 q;
    split_pack(v0, v1, q.x, q.z);   // b0: hi in .x, lo in .z
    split_pack(v2, v3, q.y, q.w);   // b1: hi in .y, lo in .w
    g_fB[w][co][j][lane] = q;
}

// ---------------- main: implicit-GEMM conv via bf16 m16n8k16 ----------------
__global__ __launch_bounds__(NTHREADS, 2)
void conv1d_bf16_mma_kernel(const float* __restrict__ x,
                            const float* __restrict__ bias,
                            float* __restrict__ out)
{
    extern __shared__ __align__(16) unsigned char smem[];
    uint32_t* xhi2   = reinterpret_cast<uint32_t*>(smem + SMEM_XHI);  // [32][PITCH2]
    uint32_t* xlo2   = reinterpret_cast<uint32_t*>(smem + SMEM_XLO);  // [32][PITCH2]
    float*    bias_s = reinterpret_cast<float*>(smem + SMEM_BIAS);

    const int tid  = threadIdx.x;
    const int lane = tid & 31;
    const int wid  = tid >> 5;        // 8 warps -> 32 t each (two 16-row m-tiles)
    const int m0   = wid * 32;
    const int n    = blockIdx.y;
    const int t0   = blockIdx.x * T_TILE;

    // ---- stage x window, pre-split bf16 hi/lo, packed in c-pairs ----
    // xhi2[cp][t] = bf16x2( x[2cp][t0+t], x[2cp+1][t0+t] ) ; xlo2 = residuals
    const float* xn = x + (size_t)n * C_TOT * WIN;
    if (t0 + XSTG <= WIN) {
        #pragma unroll
        for (int i = tid; i < 32 * 66; i += NTHREADS) {   // 66 float4 per row
            int cp = i / 66, q = i - cp * 66;
            const float* r0 = xn + (size_t)(2 * cp) * WIN + t0 + 4 * q;
            const float4 v0 = *reinterpret_cast<const float4*>(r0);
            const float4 v1 = *reinterpret_cast<const float4*>(r0 + WIN);
            uint4 h, l;
            split_pack(v0.x, v1.x, h.x, l.x);
            split_pack(v0.y, v1.y, h.y, l.y);
            split_pack(v0.z, v1.z, h.z, l.z);
            split_pack(v0.w, v1.w, h.w, l.w);
            *reinterpret_cast<uint4*>(&xhi2[cp * PITCH2 + 4 * q]) = h;
            *reinterpret_cast<uint4*>(&xlo2[cp * PITCH2 + 4 * q]) = l;
        }
    } else {
        for (int i = tid; i < 32 * XCOLS; i += NTHREADS) {
            int cp = i / XCOLS, col = i - cp * XCOLS;
            int t = t0 + col;
            float a = 0.0f, b = 0.0f;
            if (t < WIN) {
                a = xn[(size_t)(2 * cp) * WIN + t];
                b = xn[(size_t)(2 * cp + 1) * WIN + t];
            }
            uint32_t h, l;
            split_pack(a, b, h, l);
            xhi2[cp * PITCH2 + col] = h;
            xlo2[cp * PITCH2 + col] = l;
        }
    }
    if (tid < FF) bias_s[tid] = 64.0f * bias[tid];
    __syncthreads();        // the ONLY barrier

    float acc[2][8][4];
    #pragma unroll
    for (int mt = 0; mt < 2; mt++)
        #pragma unroll
        for (int j = 0; j < 8; j++)
            #pragma unroll
            for (int r = 0; r < 4; r++) acc[mt][j][r] = 0.0f;

    const int g  = lane >> 2;          // m / n sub-index
    const int k4 = lane & 3;           // k sub-index

    for (int w = 0; w < KW; ++w) {
        const int colbase = w + m0 + g;

        #pragma unroll
        for (int co = 0; co < 4; ++co) {
            // ---- A fragments, both m-tiles: 16 conflict-free LDS.32 ----
            const uint32_t* hp = &xhi2[(co * 8 + k4) * PITCH2 + colbase];
            const uint32_t* lp = &xlo2[(co * 8 + k4) * PITCH2 + colbase];
            uint32_t ah[2][4], al[2][4];
            #pragma unroll
            for (int mt = 0; mt < 2; ++mt) {
                const int o = mt * 16;
                ah[mt][0] = hp[o];               ah[mt][1] = hp[o + 8];
                ah[mt][2] = hp[4 * PITCH2 + o];  ah[mt][3] = hp[4 * PITCH2 + o + 8];
                al[mt][0] = lp[o];               al[mt][1] = lp[o + 8];
                al[mt][2] = lp[4 * PITCH2 + o];  al[mt][3] = lp[4 * PITCH2 + o + 8];
            }

            #pragma unroll
            for (int jg = 0; jg < 2; ++jg) {
                // B fragments: 4 LDG.128, identical addrs across warps/CTAs (L1/L2 hit)
                uint4 bq[4];
                #pragma unroll
                for (int jj = 0; jj < 4; ++jj)
                    bq[jj] = __ldg(&g_fB[w][co][jg * 4 + jj][lane]);
                // term hh  (same-acc reuse distance = 8 mmas)
                #pragma unroll
                for (int mt = 0; mt < 2; ++mt)
                    #pragma unroll
                    for (int jj = 0; jj < 4; ++jj)
                        mma_bf16(acc[mt][jg * 4 + jj], ah[mt], bq[jj].x, bq[jj].y);
                // term hl (A_hi * B_lo)
                #pragma unroll
                for (int mt = 0; mt < 2; ++mt)
                    #pragma unroll
                    for (int jj = 0; jj < 4; ++jj)
                        mma_bf16(acc[mt][jg * 4 + jj], ah[mt], bq[jj].z, bq[jj].w);
                // term lh (A_lo * B_hi)
                #pragma unroll
                for (int mt = 0; mt < 2; ++mt)
                    #pragma unroll
                    for (int jj = 0; jj < 4; ++jj)
                        mma_bf16(acc[mt][jg * 4 + jj], al[mt], bq[jj].x, bq[jj].y);
            }
        }
    }

    // ---- epilogue: + 64*bias[f]; 2 contiguous floats per (mt, j, row) ----
    float* on = out + (size_t)n * FF * OW;
    #pragma unroll
    for (int mt = 0; mt < 2; ++mt) {
        const int ta = t0 + m0 + mt * 16 + g;
        const int tb = ta + 8;
        #pragma unroll
        for (int j = 0; j < 8; ++j) {
            const int f0 = 8 * j + 2 * k4;
            const float bb0 = bias_s[f0], bb1 = bias_s[f0 + 1];
            if (ta < OW) {
                on[(size_t)f0 * OW + ta]       = acc[mt][j][0] + bb0;
                on[(size_t)(f0 + 1) * OW + ta] = acc[mt][j][1] + bb1;
            }
            if (tb < OW) {
                on[(size_t)f0 * OW + tb]       = acc[mt][j][2] + bb0;
                on[(size_t)(f0 + 1) * OW + tb] = acc[mt][j][3] + bb1;
            }
        }
    }
}

// =====================================================================
extern "C" void kernel_launch(void* const* d_in, const int* in_sizes, int n_in,
                              void* d_out, int out_size) {
    const float* x    = (const float*)d_in[0];   // [64,64,4096]
    const float* filt = (const float*)d_in[1];   // [64,64,9]
    const float* bias = (const float*)d_in[2];   // [64]
    float* out = (float*)d_out;                  // [64,64,4088]

    cudaFuncSetAttribute(conv1d_bf16_mma_kernel,
                         cudaFuncAttributeMaxDynamicSharedMemorySize, SMEM_TOTAL);

    prep_filter_bf16<<<(KW * 1024 + 255) / 256, 256>>>(filt);

    dim3 grid((OW + T_TILE - 1) / T_TILE, NN);   // (16, 64)
    conv1d_bf16_mma_kernel<<<grid, NTHREADS, SMEM_TOTAL>>>(x, bias, out);
}

// round 13
// speedup vs baseline: 6.2853x; 1.4016x over previous
#include <cuda_runtime.h>
#include <cuda_fp16.h>
#include <cstdint>

// ---------------- problem constants ----------------
#define NN      64
#define C_TOT   64
#define WIN     4096
#define FF      64
#define KW      9
#define OW      4088
#define T_TILE  256
#define XCOLS   263          // T_TILE + 8 - 1  (max col actually read)
#define XSTG    264          // staged cols in full path (mult of 4)
#define PITCH2  264          // 264 mod 32 == 8 -> banks 8*k4+g all distinct
#define NTHREADS 256

// smem layout (dynamic)
#define SMEM_XH     0                          // 32*264*4 = 33792 B (f16x2 c-pairs)
#define SMEM_BIAS   33792                      // 256 B
#define SMEM_TOTAL  34048

// pre-split fp16 filter in B-fragment order:
// g_fB[w][co(4)][j(8)][lane(32)] = {bhi0, bhi1, blo0, blo1}
__device__ uint4 g_fB[KW][4][8][32];

// pack two f32 -> f16x2; first arg -> LOW half (channel 2cp), second -> HIGH
__device__ __forceinline__ uint32_t pack_f16x2(float lo_elem, float hi_elem) {
    uint32_t r;
    asm("cvt.rn.f16x2.f32 %0, %1, %2;" : "=r"(r) : "f"(hi_elem), "f"(lo_elem));
    return r;
}
__device__ __forceinline__ float f16_lo(uint32_t p) {
    return __half2float(__ushort_as_half((unsigned short)(p & 0xFFFF)));
}
__device__ __forceinline__ float f16_hi(uint32_t p) {
    return __half2float(__ushort_as_half((unsigned short)(p >> 16)));
}
// hi = fp16 RN pair; lo = fp16 RN pair of residuals (used for B only)
__device__ __forceinline__ void split_pack(float v0, float v1,
                                           uint32_t& hi, uint32_t& lo) {
    hi = pack_f16x2(v0, v1);
    lo = pack_f16x2(v0 - f16_lo(hi), v1 - f16_hi(hi));
}

__device__ __forceinline__ void mma_f16(float* d, const uint32_t* a,
                                        uint32_t b0, uint32_t b1) {
    asm volatile(
        "mma.sync.aligned.m16n8k16.row.col.f32.f16.f16.f32 "
        "{%0,%1,%2,%3}, {%4,%5,%6,%7}, {%8,%9}, {%0,%1,%2,%3};"
        : "+f"(d[0]), "+f"(d[1]), "+f"(d[2]), "+f"(d[3])
        : "r"(a[0]), "r"(a[1]), "r"(a[2]), "r"(a[3]), "r"(b0), "r"(b1));
}

// ---------------- prep: split filter into fragment-ordered fp16 hi/lo ----------------
__global__ void prep_filter_f16(const float* __restrict__ filt) {
    int e = blockIdx.x * blockDim.x + threadIdx.x;
    if (e >= KW * 4 * 8 * 32) return;
    int w    = e / 1024;
    int rem  = e - w * 1024;
    int co   = rem >> 8;
    int j    = (rem >> 5) & 7;
    int lane = rem & 31;
    int g = lane >> 2, k4 = lane & 3;
    int f  = 8 * j + g;
    int c0 = co * 16 + 2 * k4;

    const float* fr = filt + (size_t)f * (C_TOT * KW) + w;
    float v0 = fr[(c0    ) * KW];
    float v1 = fr[(c0 + 1) * KW];
    float v2 = fr[(c0 + 8) * KW];
    float v3 = fr[(c0 + 9) * KW];

    uint4 q;
    split_pack(v0, v1, q.x, q.z);   // b0: hi in .x, lo in .z
    split_pack(v2, v3, q.y, q.w);   // b1: hi in .y, lo in .w
    g_fB[w][co][j][lane] = q;
}

// ---------------- main: implicit-GEMM conv via fp16 m16n8k16, 2-term ----------------
__global__ __launch_bounds__(NTHREADS, 2)
void conv1d_f16_mma_kernel(const float* __restrict__ x,
                           const float* __restrict__ bias,
                           float* __restrict__ out)
{
    extern __shared__ __align__(16) unsigned char smem[];
    uint32_t* xh2    = reinterpret_cast<uint32_t*>(smem + SMEM_XH);  // [32][PITCH2]
    float*    bias_s = reinterpret_cast<float*>(smem + SMEM_BIAS);

    const int tid  = threadIdx.x;
    const int lane = tid & 31;
    const int wid  = tid >> 5;        // 8 warps -> 32 t each (two 16-row m-tiles)
    const int m0   = wid * 32;
    const int n    = blockIdx.y;
    const int t0   = blockIdx.x * T_TILE;

    // ---- stage x window as fp16 c-pair packs: xh2[cp][t]=f16x2(x[2cp],x[2cp+1]) ----
    const float* xn = x + (size_t)n * C_TOT * WIN;
    if (t0 + XSTG <= WIN) {
        #pragma unroll
        for (int i = tid; i < 32 * 66; i += NTHREADS) {   // 66 float4 per row
            int cp = i / 66, q = i - cp * 66;
            const float* r0 = xn + (size_t)(2 * cp) * WIN + t0 + 4 * q;
            const float4 v0 = *reinterpret_cast<const float4*>(r0);
            const float4 v1 = *reinterpret_cast<const float4*>(r0 + WIN);
            uint4 h;
            h.x = pack_f16x2(v0.x, v1.x);
            h.y = pack_f16x2(v0.y, v1.y);
            h.z = pack_f16x2(v0.z, v1.z);
            h.w = pack_f16x2(v0.w, v1.w);
            *reinterpret_cast<uint4*>(&xh2[cp * PITCH2 + 4 * q]) = h;
        }
    } else {
        for (int i = tid; i < 32 * XCOLS; i += NTHREADS) {
            int cp = i / XCOLS, col = i - cp * XCOLS;
            int t = t0 + col;
            float a = 0.0f, b = 0.0f;
            if (t < WIN) {
                a = xn[(size_t)(2 * cp) * WIN + t];
                b = xn[(size_t)(2 * cp + 1) * WIN + t];
            }
            xh2[cp * PITCH2 + col] = pack_f16x2(a, b);
        }
    }
    if (tid < FF) bias_s[tid] = 64.0f * bias[tid];
    __syncthreads();        // the ONLY barrier

    float acc[2][8][4];
    #pragma unroll
    for (int mt = 0; mt < 2; mt++)
        #pragma unroll
        for (int j = 0; j < 8; j++)
            #pragma unroll
            for (int r = 0; r < 4; r++) acc[mt][j][r] = 0.0f;

    const int g  = lane >> 2;          // m / n sub-index
    const int k4 = lane & 3;           // k sub-index

    for (int w = 0; w < KW; ++w) {
        const int colbase = w + m0 + g;

        #pragma unroll
        for (int co = 0; co < 4; ++co) {
            // ---- A fragments, both m-tiles: 8 conflict-free LDS.32 ----
            const uint32_t* hp = &xh2[(co * 8 + k4) * PITCH2 + colbase];
            uint32_t ah[2][4];
            #pragma unroll
            for (int mt = 0; mt < 2; ++mt) {
                const int o = mt * 16;
                ah[mt][0] = hp[o];               ah[mt][1] = hp[o + 8];
                ah[mt][2] = hp[4 * PITCH2 + o];  ah[mt][3] = hp[4 * PITCH2 + o + 8];
            }

            #pragma unroll
            for (int jg = 0; jg < 2; ++jg) {
                // B fragments: 4 LDG.128, identical addrs across warps/CTAs (L1/L2 hit)
                uint4 bq[4];
                #pragma unroll
                for (int jj = 0; jj < 4; ++jj)
                    bq[jj] = __ldg(&g_fB[w][co][jg * 4 + jj][lane]);
                // term A*B_hi   (same-acc reuse distance = 8 mmas)
                #pragma unroll
                for (int mt = 0; mt < 2; ++mt)
                    #pragma unroll
                    for (int jj = 0; jj < 4; ++jj)
                        mma_f16(acc[mt][jg * 4 + jj], ah[mt], bq[jj].x, bq[jj].y);
                // term A*B_lo
                #pragma unroll
                for (int mt = 0; mt < 2; ++mt)
                    #pragma unroll
                    for (int jj = 0; jj < 4; ++jj)
                        mma_f16(acc[mt][jg * 4 + jj], ah[mt], bq[jj].z, bq[jj].w);
            }
        }
    }

    // ---- epilogue: + 64*bias[f]; 2 contiguous floats per (mt, j, row) ----
    float* on = out + (size_t)n * FF * OW;
    #pragma unroll
    for (int mt = 0; mt < 2; ++mt) {
        const int ta = t0 + m0 + mt * 16 + g;
        const int tb = ta + 8;
        #pragma unroll
        for (int j = 0; j < 8; ++j) {
            const int f0 = 8 * j + 2 * k4;
            const float bb0 = bias_s[f0], bb1 = bias_s[f0 + 1];
            if (ta < OW) {
                on[(size_t)f0 * OW + ta]       = acc[mt][j][0] + bb0;
                on[(size_t)(f0 + 1) * OW + ta] = acc[mt][j][1] + bb1;
            }
            if (tb < OW) {
                on[(size_t)f0 * OW + tb]       = acc[mt][j][2] + bb0;
                on[(size_t)(f0 + 1) * OW + tb] = acc[mt][j][3] + bb1;
            }
        }
    }
}

// =====================================================================
extern "C" void kernel_launch(void* const* d_in, const int* in_sizes, int n_in,
                              void* d_out, int out_size) {
    const float* x    = (const float*)d_in[0];   // [64,64,4096]
    const float* filt = (const float*)d_in[1];   // [64,64,9]
    const float* bias = (const float*)d_in[2];   // [64]
    float* out = (float*)d_out;                  // [64,64,4088]

    cudaFuncSetAttribute(conv1d_f16_mma_kernel,
                         cudaFuncAttributeMaxDynamicSharedMemorySize, SMEM_TOTAL);

    prep_filter_f16<<<(KW * 1024 + 255) / 256, 256>>>(filt);

    dim3 grid((OW + T_TILE - 1) / T_TILE, NN);   // (16, 64)
    conv1d_f16_mma_kernel<<<grid, NTHREADS, SMEM_TOTAL>>>(x, bias, out);
}